// round 14
// baseline (speedup 1.0000x reference)
#include <cuda_runtime.h>
#include <cuda_bf16.h>

// B=8192, L=1, K=32, H=1024. Single fused kernel, grid 8192.
// R11: launch_bounds(256,8) pins regs to 32 so the barrier-free stream keeps
// 8 CTAs/SM (k1's proven 86%-HBM operating point). MLP tail (last-arriving
// CTA per 16-batch group) kept ROLLED so its register pressure can't leak
// into the streaming loop; it runs in 512/8192 CTAs, overlapped.

#define KK 32
#define HH 1024
#define BB 8192
#define GRP 16                     // batches per MLP group

__device__ float g_cd[BB * KK];    // sqrt'd context distances (1 MB)
__device__ int   g_cnt[BB / GRP];  // zero-init; last arriver resets to 0

__global__ __launch_bounds__(256, 8) void mu_fused(
    const int*   __restrict__ vals,
    const float* __restrict__ distances,
    const float* __restrict__ cache_hidden,
    const float* __restrict__ hiddens,
    const float* __restrict__ W1,
    const float* __restrict__ b1,
    const float* __restrict__ W2,
    const float* __restrict__ b2,
    float* __restrict__ out, int N)
{
    const int b    = blockIdx.x;
    const int tid  = threadIdx.x;
    const int warp = tid >> 5;
    const int lane = tid & 31;

    // ---------------- barrier-free streaming cdist (== k1) ----------------
    {
        const float4* C4    = (const float4*)(cache_hidden + (size_t)b * HH);
        const float4* Hbase = (const float4*)(hiddens + (size_t)b * KK * HH)
                            + (size_t)warp * 4 * 256;

        float a0 = 0.f, a1 = 0.f, a2 = 0.f, a3 = 0.f;
        #pragma unroll
        for (int it = 0; it < 8; it++) {
            int idx = it * 32 + lane;
            float4 c  = __ldg(&C4[idx]);
            float4 x0 = __ldcs(Hbase + idx);
            float4 x1 = __ldcs(Hbase + 256 + idx);
            float4 x2 = __ldcs(Hbase + 512 + idx);
            float4 x3 = __ldcs(Hbase + 768 + idx);
            float d;
            d = c.x - x0.x; a0 += d * d;  d = c.y - x0.y; a0 += d * d;
            d = c.z - x0.z; a0 += d * d;  d = c.w - x0.w; a0 += d * d;
            d = c.x - x1.x; a1 += d * d;  d = c.y - x1.y; a1 += d * d;
            d = c.z - x1.z; a1 += d * d;  d = c.w - x1.w; a1 += d * d;
            d = c.x - x2.x; a2 += d * d;  d = c.y - x2.y; a2 += d * d;
            d = c.z - x2.z; a2 += d * d;  d = c.w - x2.w; a2 += d * d;
            d = c.x - x3.x; a3 += d * d;  d = c.y - x3.y; a3 += d * d;
            d = c.z - x3.z; a3 += d * d;  d = c.w - x3.w; a3 += d * d;
        }
        #pragma unroll
        for (int o = 16; o; o >>= 1) {
            a0 += __shfl_xor_sync(0xffffffffu, a0, o);
            a1 += __shfl_xor_sync(0xffffffffu, a1, o);
            a2 += __shfl_xor_sync(0xffffffffu, a2, o);
            a3 += __shfl_xor_sync(0xffffffffu, a3, o);
        }
        if (lane < 4) {
            float a = (lane == 0) ? a0 : (lane == 1) ? a1 : (lane == 2) ? a2 : a3;
            g_cd[b * KK + warp * 4 + lane] = sqrtf(a);
        }
    }

    // ---------------- group arrival: last CTA of 16 runs the MLP ----------------
    __shared__ int s_last;
    __syncthreads();                       // all warps' g_cd writes issued
    if (tid == 0) {
        __threadfence();                   // release g_cd
        int old = atomicAdd(&g_cnt[b >> 4], 1);
        s_last = (old == GRP - 1);
        if (old == GRP - 1) {
            g_cnt[b >> 4] = 0;             // replay-safe reset
            __threadfence();               // acquire side for g_cd reads
        }
    }
    __syncthreads();
    if (!s_last) return;

    // ---------------- MLP for batches [gb0, gb0+16), kept LOW-PRESSURE ----------------
    __shared__ __align__(16) float sx[GRP][96];
    __shared__ float shid[GRP][64];
    const int gb0 = (b >> 4) << 4;

    // warps 0-7 assemble 2 batches each (rolled)
    #pragma unroll 1
    for (int q = 0; q < 2; q++) {
        const int j  = warp * 2 + q;
        const int bb = gb0 + j;
        sx[j][lane]      = g_cd[bb * KK + lane];
        sx[j][32 + lane] = distances[bb * KK + lane];
        int v = vals[bb * KK + lane];
        unsigned m = __match_any_sync(0xffffffffu, v);
        int isnew = (v != 0) && ((m & ((1u << lane) - 1u)) == 0);
        int cnt = isnew;
        #pragma unroll
        for (int o = 1; o < 32; o <<= 1) {
            int t = __shfl_up_sync(0xffffffffu, cnt, o);
            if (lane >= o) cnt += t;
        }
        sx[j][64 + lane] = (float)cnt;
    }
    __syncthreads();

    // layer 1: thread = (neuron n, group g of 4 batches); rolled i-loop
    {
        const int n = tid & 63;
        const int g = tid >> 6;
        const float4* w4 = (const float4*)(W1 + n * 96);
        const float4* xa = (const float4*)sx[g * 4 + 0];
        const float4* xb = (const float4*)sx[g * 4 + 1];
        const float4* xc = (const float4*)sx[g * 4 + 2];
        const float4* xd = (const float4*)sx[g * 4 + 3];
        const float bias = __ldg(&b1[n]);
        float acc0 = bias, acc1 = bias, acc2 = bias, acc3 = bias;
        #pragma unroll 1
        for (int i = 0; i < 24; i++) {
            float4 w = __ldg(&w4[i]);
            float4 x;
            x = xa[i]; acc0 += w.x * x.x + w.y * x.y + w.z * x.z + w.w * x.w;
            x = xb[i]; acc1 += w.x * x.x + w.y * x.y + w.z * x.z + w.w * x.w;
            x = xc[i]; acc2 += w.x * x.x + w.y * x.y + w.z * x.z + w.w * x.w;
            x = xd[i]; acc3 += w.x * x.x + w.y * x.y + w.z * x.z + w.w * x.w;
        }
        shid[g * 4 + 0][n] = tanhf(acc0);
        shid[g * 4 + 1][n] = tanhf(acc1);
        shid[g * 4 + 2][n] = tanhf(acc2);
        shid[g * 4 + 3][n] = tanhf(acc3);
    }
    __syncthreads();

    // layer 2 + sigmoid + scale + write: warp w handles batches 2w, 2w+1 (rolled)
    {
        const float w2a = __ldg(&W2[lane]);
        const float w2b = __ldg(&W2[lane + 32]);
        const float bb2 = __ldg(&b2[0]);
        #pragma unroll 1
        for (int q = 0; q < 2; q++) {
            const int j = warp * 2 + q;
            float s = shid[j][lane] * w2a + shid[j][lane + 32] * w2b;
            #pragma unroll
            for (int o = 16; o; o >>= 1) s += __shfl_xor_sync(0xffffffffu, s, o);
            s += bb2;
            float mu = 1.f / (1.f + expf(-s));
            float scale = __shfl_sync(0xffffffffu, 5.f * mu, 0);
            float cd = sx[j][lane] * scale;
            int o0 = (gb0 + j) * KK + lane;
            out[o0]     = cd;
            out[N + o0] = sx[j][32 + lane] + cd;
        }
    }
}

extern "C" void kernel_launch(void* const* d_in, const int* in_sizes, int n_in,
                              void* d_out, int out_size)
{
    const int*   vals         = (const int*)  d_in[0];
    const float* distances    = (const float*)d_in[1];
    const float* cache_hidden = (const float*)d_in[2];
    const float* hiddens      = (const float*)d_in[3];
    const float* W1           = (const float*)d_in[4];
    const float* b1           = (const float*)d_in[5];
    const float* W2           = (const float*)d_in[6];
    const float* b2           = (const float*)d_in[7];
    float* out = (float*)d_out;

    int N = in_sizes[1];              // B*L*K = 262144
    int B = N / KK;                   // 8192

    mu_fused<<<B, 256>>>(vals, distances, cache_hidden, hiddens,
                         W1, b1, W2, b2, out, N);
}

// round 16
// speedup vs baseline: 1.0080x; 1.0080x over previous
#include <cuda_runtime.h>
#include <cuda_bf16.h>

// B=8192, L=1, K=32, H=1024.
// k1: PERSISTENT barrier-free cdist stream. grid=1216 (~8 CTAs/SM), each CTA
//     grid-strides over batches. No wave transitions; next-batch loads are
//     independent of the current batch's reduction drain, so the load pipe
//     never starves at batch boundaries.
// k2: R9 MLP tail (16 batches/CTA, smem W1, 4-batch-shared w reads). Proven 12.5us.

#define KK 32
#define HH 1024
#define BB 8192
#define PGRID 1216   // 152 SMs x 8 resident CTAs

__device__ float g_cd[BB * KK];   // scratch: sqrt'd context distances (1 MB)

// ---------------- Kernel 1: persistent streaming cdist ----------------
__global__ __launch_bounds__(256, 8) void cdist_kernel(
    const float* __restrict__ cache_hidden,
    const float* __restrict__ hiddens)
{
    const int warp = threadIdx.x >> 5;
    const int lane = threadIdx.x & 31;

    for (int b = blockIdx.x; b < BB; b += PGRID) {
        const float4* C4    = (const float4*)(cache_hidden + (size_t)b * HH);
        const float4* Hbase = (const float4*)(hiddens + (size_t)b * KK * HH)
                            + (size_t)warp * 4 * 256;

        float a0 = 0.f, a1 = 0.f, a2 = 0.f, a3 = 0.f;
        #pragma unroll
        for (int it = 0; it < 8; it++) {
            int idx = it * 32 + lane;                  // coalesced 512B per LDG
            float4 c  = __ldg(&C4[idx]);
            float4 x0 = __ldcs(Hbase + idx);
            float4 x1 = __ldcs(Hbase + 256 + idx);
            float4 x2 = __ldcs(Hbase + 512 + idx);
            float4 x3 = __ldcs(Hbase + 768 + idx);
            float d;
            d = c.x - x0.x; a0 += d * d;  d = c.y - x0.y; a0 += d * d;
            d = c.z - x0.z; a0 += d * d;  d = c.w - x0.w; a0 += d * d;
            d = c.x - x1.x; a1 += d * d;  d = c.y - x1.y; a1 += d * d;
            d = c.z - x1.z; a1 += d * d;  d = c.w - x1.w; a1 += d * d;
            d = c.x - x2.x; a2 += d * d;  d = c.y - x2.y; a2 += d * d;
            d = c.z - x2.z; a2 += d * d;  d = c.w - x2.w; a2 += d * d;
            d = c.x - x3.x; a3 += d * d;  d = c.y - x3.y; a3 += d * d;
            d = c.z - x3.z; a3 += d * d;  d = c.w - x3.w; a3 += d * d;
        }
        #pragma unroll
        for (int o = 16; o; o >>= 1) {
            a0 += __shfl_xor_sync(0xffffffffu, a0, o);
            a1 += __shfl_xor_sync(0xffffffffu, a1, o);
            a2 += __shfl_xor_sync(0xffffffffu, a2, o);
            a3 += __shfl_xor_sync(0xffffffffu, a3, o);
        }
        if (lane < 4) {
            float a = (lane == 0) ? a0 : (lane == 1) ? a1 : (lane == 2) ? a2 : a3;
            g_cd[b * KK + warp * 4 + lane] = sqrtf(a);
        }
    }
}

// ---------------- Kernel 2: MLP tail, 16 batches per CTA (R9) ----------------
#define W1S 100   // padded row stride (floats); conflict-free LDS.128
#define JB  16    // batches per CTA

__global__ __launch_bounds__(256, 3) void mlp_kernel(
    const int*   __restrict__ vals,
    const float* __restrict__ distances,
    const float* __restrict__ W1,
    const float* __restrict__ b1,
    const float* __restrict__ W2,
    const float* __restrict__ b2,
    float* __restrict__ out, int N)
{
    __shared__ __align__(16) float sW1[64 * W1S];   // 25.6 KB
    __shared__ __align__(16) float sx[JB][96];      // 6 KB
    __shared__ float shid[JB][64];                  // 4 KB

    const int b0   = blockIdx.x * JB;
    const int tid  = threadIdx.x;
    const int warp = tid >> 5;
    const int lane = tid & 31;

    // stage W1: 1536 float4, coalesced, rows repadded to stride 100
    {
        const float4* g = (const float4*)W1;
        #pragma unroll
        for (int i = 0; i < 6; i++) {
            int m4 = tid + i * 256;
            float4 v = g[m4];
            int m = m4 * 4;
            int r = m / 96, c = m - r * 96;          // float4 never crosses a row
            *(float4*)&sW1[r * W1S + c] = v;
        }
    }

    // warps 0-7: assemble inputs for batches 2*warp, 2*warp+1
    #pragma unroll
    for (int q = 0; q < 2; q++) {
        const int j  = warp * 2 + q;
        const int bb = b0 + j;
        sx[j][lane]      = g_cd[bb * KK + lane];
        sx[j][32 + lane] = distances[bb * KK + lane];
        int v = vals[bb * KK + lane];
        unsigned m = __match_any_sync(0xffffffffu, v);
        int isnew = (v != 0) && ((m & ((1u << lane) - 1u)) == 0);
        int cnt = isnew;
        #pragma unroll
        for (int o = 1; o < 32; o <<= 1) {
            int t = __shfl_up_sync(0xffffffffu, cnt, o);
            if (lane >= o) cnt += t;
        }
        sx[j][64 + lane] = (float)cnt;
    }
    __syncthreads();

    // layer 1: thread = (neuron n, group g); group g computes batches 4g..4g+3.
    {
        const int n = tid & 63;
        const int g = tid >> 6;                      // 0..3
        const float4* w4 = (const float4*)&sW1[n * W1S];
        const float4* xa = (const float4*)sx[g * 4 + 0];
        const float4* xb = (const float4*)sx[g * 4 + 1];
        const float4* xc = (const float4*)sx[g * 4 + 2];
        const float4* xd = (const float4*)sx[g * 4 + 3];
        const float bias = __ldg(&b1[n]);
        float acc0 = bias, acc1 = bias, acc2 = bias, acc3 = bias;
        #pragma unroll
        for (int i = 0; i < 24; i++) {
            float4 w = w4[i];
            float4 x;
            x = xa[i]; acc0 += w.x * x.x + w.y * x.y + w.z * x.z + w.w * x.w;
            x = xb[i]; acc1 += w.x * x.x + w.y * x.y + w.z * x.z + w.w * x.w;
            x = xc[i]; acc2 += w.x * x.x + w.y * x.y + w.z * x.z + w.w * x.w;
            x = xd[i]; acc3 += w.x * x.x + w.y * x.y + w.z * x.z + w.w * x.w;
        }
        shid[g * 4 + 0][n] = tanhf(acc0);
        shid[g * 4 + 1][n] = tanhf(acc1);
        shid[g * 4 + 2][n] = tanhf(acc2);
        shid[g * 4 + 3][n] = tanhf(acc3);
    }
    __syncthreads();

    // layer 2 + sigmoid + scale + write: warp w handles batches 2w, 2w+1
    {
        const float w2a = __ldg(&W2[lane]);
        const float w2b = __ldg(&W2[lane + 32]);
        const float bb2 = __ldg(&b2[0]);
        #pragma unroll
        for (int q = 0; q < 2; q++) {
            const int j = warp * 2 + q;
            float s = shid[j][lane] * w2a + shid[j][lane + 32] * w2b;
            #pragma unroll
            for (int o = 16; o; o >>= 1) s += __shfl_xor_sync(0xffffffffu, s, o);
            s += bb2;
            float mu = 1.f / (1.f + expf(-s));
            float scale = __shfl_sync(0xffffffffu, 5.f * mu, 0);
            float cd = sx[j][lane] * scale;
            int o0 = (b0 + j) * KK + lane;
            out[o0]     = cd;
            out[N + o0] = sx[j][32 + lane] + cd;
        }
    }
}

extern "C" void kernel_launch(void* const* d_in, const int* in_sizes, int n_in,
                              void* d_out, int out_size)
{
    const int*   vals         = (const int*)  d_in[0];
    const float* distances    = (const float*)d_in[1];
    const float* cache_hidden = (const float*)d_in[2];
    const float* hiddens      = (const float*)d_in[3];
    const float* W1           = (const float*)d_in[4];
    const float* b1           = (const float*)d_in[5];
    const float* W2           = (const float*)d_in[6];
    const float* b2           = (const float*)d_in[7];
    float* out = (float*)d_out;

    int N = in_sizes[1];              // B*L*K = 262144
    int B = N / KK;                   // 8192

    cdist_kernel<<<PGRID, 256>>>(cache_hidden, hiddens);
    mlp_kernel<<<B / JB, 256>>>(vals, distances, W1, b1, W2, b2, out, N);
}

// round 17
// speedup vs baseline: 1.0413x; 1.0330x over previous
#include <cuda_runtime.h>
#include <cuda_bf16.h>

// B=8192, L=1, K=32, H=1024.
// k1: R9 wave-scheduled barrier-free cdist stream (1 GiB, ~86% HBM). FROZEN.
// k2: PDL-overlapped MLP tail. Launched with programmatic stream serialization:
//     pre-sync it stages W1, assembles [dist|counts], and computes the 2/3 of
//     layer-1 that doesn't need cdist. cudaGridDependencySynchronize(), then
//     only the cd-third + tanh + layer-2 (~3us) is exposed after k1.

#define KK 32
#define HH 1024
#define BB 8192

__device__ float g_cd[BB * KK];   // scratch: sqrt'd context distances (1 MB)

// ---------------- Kernel 1: streaming cdist, one CTA per batch ----------------
__global__ __launch_bounds__(256, 8) void cdist_kernel(
    const float* __restrict__ cache_hidden,
    const float* __restrict__ hiddens)
{
    const int b    = blockIdx.x;
    const int warp = threadIdx.x >> 5;
    const int lane = threadIdx.x & 31;

    const float4* C4    = (const float4*)(cache_hidden + (size_t)b * HH);
    const float4* Hbase = (const float4*)(hiddens + (size_t)b * KK * HH)
                        + (size_t)warp * 4 * 256;

    float a0 = 0.f, a1 = 0.f, a2 = 0.f, a3 = 0.f;
    #pragma unroll
    for (int it = 0; it < 8; it++) {
        int idx = it * 32 + lane;                  // coalesced 512B per LDG
        float4 c  = __ldg(&C4[idx]);
        float4 x0 = __ldcs(Hbase + idx);
        float4 x1 = __ldcs(Hbase + 256 + idx);
        float4 x2 = __ldcs(Hbase + 512 + idx);
        float4 x3 = __ldcs(Hbase + 768 + idx);
        float d;
        d = c.x - x0.x; a0 += d * d;  d = c.y - x0.y; a0 += d * d;
        d = c.z - x0.z; a0 += d * d;  d = c.w - x0.w; a0 += d * d;
        d = c.x - x1.x; a1 += d * d;  d = c.y - x1.y; a1 += d * d;
        d = c.z - x1.z; a1 += d * d;  d = c.w - x1.w; a1 += d * d;
        d = c.x - x2.x; a2 += d * d;  d = c.y - x2.y; a2 += d * d;
        d = c.z - x2.z; a2 += d * d;  d = c.w - x2.w; a2 += d * d;
        d = c.x - x3.x; a3 += d * d;  d = c.y - x3.y; a3 += d * d;
        d = c.z - x3.z; a3 += d * d;  d = c.w - x3.w; a3 += d * d;
    }
    #pragma unroll
    for (int o = 16; o; o >>= 1) {
        a0 += __shfl_xor_sync(0xffffffffu, a0, o);
        a1 += __shfl_xor_sync(0xffffffffu, a1, o);
        a2 += __shfl_xor_sync(0xffffffffu, a2, o);
        a3 += __shfl_xor_sync(0xffffffffu, a3, o);
    }
    if (lane < 4) {
        float a = (lane == 0) ? a0 : (lane == 1) ? a1 : (lane == 2) ? a2 : a3;
        g_cd[b * KK + warp * 4 + lane] = sqrtf(a);
    }
}

// ---------------- Kernel 2: PDL MLP tail, 16 batches per CTA ----------------
#define W1S 100   // padded row stride (floats); conflict-free LDS.128
#define JB  16    // batches per CTA

__global__ __launch_bounds__(256, 3) void mlp_kernel(
    const int*   __restrict__ vals,
    const float* __restrict__ distances,
    const float* __restrict__ W1,
    const float* __restrict__ b1,
    const float* __restrict__ W2,
    const float* __restrict__ b2,
    float* __restrict__ out, int N)
{
    __shared__ __align__(16) float sW1[64 * W1S];   // 25.6 KB
    __shared__ __align__(16) float sx[JB][96];      // 6 KB
    __shared__ float accp[JB][64];                  // partial layer-1 accumulators
    __shared__ float shid[JB][64];

    const int b0   = blockIdx.x * JB;
    const int tid  = threadIdx.x;
    const int warp = tid >> 5;
    const int lane = tid & 31;

    // ======== PRE-SYNC: everything independent of k1 ========

    // stage W1 (rows repadded to stride 100)
    {
        const float4* g = (const float4*)W1;
        #pragma unroll
        for (int i = 0; i < 6; i++) {
            int m4 = tid + i * 256;
            float4 v = g[m4];
            int m = m4 * 4;
            int r = m / 96, c = m - r * 96;
            *(float4*)&sW1[r * W1S + c] = v;
        }
    }

    // warps 0-7: distances + label counts for batches 2w, 2w+1
    #pragma unroll
    for (int q = 0; q < 2; q++) {
        const int j  = warp * 2 + q;
        const int bb = b0 + j;
        sx[j][32 + lane] = distances[bb * KK + lane];
        int v = vals[bb * KK + lane];
        unsigned m = __match_any_sync(0xffffffffu, v);
        int isnew = (v != 0) && ((m & ((1u << lane) - 1u)) == 0);
        int cnt = isnew;
        #pragma unroll
        for (int o = 1; o < 32; o <<= 1) {
            int t = __shfl_up_sync(0xffffffffu, cnt, o);
            if (lane >= o) cnt += t;
        }
        sx[j][64 + lane] = (float)cnt;
    }
    __syncthreads();

    // partial layer 1 over x[32:96] (float4 i = 8..23); group g -> batches 4g..4g+3
    {
        const int n = tid & 63;
        const int g = tid >> 6;
        const float4* w4 = (const float4*)&sW1[n * W1S];
        const float4* xa = (const float4*)sx[g * 4 + 0];
        const float4* xb = (const float4*)sx[g * 4 + 1];
        const float4* xc = (const float4*)sx[g * 4 + 2];
        const float4* xd = (const float4*)sx[g * 4 + 3];
        const float bias = __ldg(&b1[n]);
        float acc0 = bias, acc1 = bias, acc2 = bias, acc3 = bias;
        #pragma unroll
        for (int i = 8; i < 24; i++) {
            float4 w = w4[i];
            float4 x;
            x = xa[i]; acc0 += w.x * x.x + w.y * x.y + w.z * x.z + w.w * x.w;
            x = xb[i]; acc1 += w.x * x.x + w.y * x.y + w.z * x.z + w.w * x.w;
            x = xc[i]; acc2 += w.x * x.x + w.y * x.y + w.z * x.z + w.w * x.w;
            x = xd[i]; acc3 += w.x * x.x + w.y * x.y + w.z * x.z + w.w * x.w;
        }
        accp[g * 4 + 0][n] = acc0;
        accp[g * 4 + 1][n] = acc1;
        accp[g * 4 + 2][n] = acc2;
        accp[g * 4 + 3][n] = acc3;
    }

    // ======== WAIT for k1 grid ========
    cudaGridDependencySynchronize();

    // load cd (now valid): warps 0-7, 2 batches each
    #pragma unroll
    for (int q = 0; q < 2; q++) {
        const int j = warp * 2 + q;
        sx[j][lane] = g_cd[(b0 + j) * KK + lane];
    }
    __syncthreads();

    // finish layer 1 over x[0:32] (float4 i = 0..7) + tanh
    {
        const int n = tid & 63;
        const int g = tid >> 6;
        const float4* w4 = (const float4*)&sW1[n * W1S];
        const float4* xa = (const float4*)sx[g * 4 + 0];
        const float4* xb = (const float4*)sx[g * 4 + 1];
        const float4* xc = (const float4*)sx[g * 4 + 2];
        const float4* xd = (const float4*)sx[g * 4 + 3];
        float acc0 = accp[g * 4 + 0][n];
        float acc1 = accp[g * 4 + 1][n];
        float acc2 = accp[g * 4 + 2][n];
        float acc3 = accp[g * 4 + 3][n];
        #pragma unroll
        for (int i = 0; i < 8; i++) {
            float4 w = w4[i];
            float4 x;
            x = xa[i]; acc0 += w.x * x.x + w.y * x.y + w.z * x.z + w.w * x.w;
            x = xb[i]; acc1 += w.x * x.x + w.y * x.y + w.z * x.z + w.w * x.w;
            x = xc[i]; acc2 += w.x * x.x + w.y * x.y + w.z * x.z + w.w * x.w;
            x = xd[i]; acc3 += w.x * x.x + w.y * x.y + w.z * x.z + w.w * x.w;
        }
        shid[g * 4 + 0][n] = tanhf(acc0);
        shid[g * 4 + 1][n] = tanhf(acc1);
        shid[g * 4 + 2][n] = tanhf(acc2);
        shid[g * 4 + 3][n] = tanhf(acc3);
    }
    __syncthreads();

    // layer 2 + sigmoid + scale + write
    {
        const float w2a = __ldg(&W2[lane]);
        const float w2b = __ldg(&W2[lane + 32]);
        const float bb2 = __ldg(&b2[0]);
        #pragma unroll
        for (int q = 0; q < 2; q++) {
            const int j = warp * 2 + q;
            float s = shid[j][lane] * w2a + shid[j][lane + 32] * w2b;
            #pragma unroll
            for (int o = 16; o; o >>= 1) s += __shfl_xor_sync(0xffffffffu, s, o);
            s += bb2;
            float mu = 1.f / (1.f + expf(-s));
            float scale = __shfl_sync(0xffffffffu, 5.f * mu, 0);
            float cd = sx[j][lane] * scale;
            int o0 = (b0 + j) * KK + lane;
            out[o0]     = cd;
            out[N + o0] = sx[j][32 + lane] + cd;
        }
    }
}

extern "C" void kernel_launch(void* const* d_in, const int* in_sizes, int n_in,
                              void* d_out, int out_size)
{
    const int*   vals         = (const int*)  d_in[0];
    const float* distances    = (const float*)d_in[1];
    const float* cache_hidden = (const float*)d_in[2];
    const float* hiddens      = (const float*)d_in[3];
    const float* W1           = (const float*)d_in[4];
    const float* b1           = (const float*)d_in[5];
    const float* W2           = (const float*)d_in[6];
    const float* b2           = (const float*)d_in[7];
    float* out = (float*)d_out;

    int N = in_sizes[1];              // B*L*K = 262144
    int B = N / KK;                   // 8192

    cdist_kernel<<<B, 256>>>(cache_hidden, hiddens);

    // k2 with programmatic dependent launch: overlaps its pre-sync section
    // with k1's tail; cudaGridDependencySynchronize() guards g_cd reads.
    {
        cudaLaunchConfig_t cfg = {};
        cfg.gridDim  = dim3(B / JB, 1, 1);
        cfg.blockDim = dim3(256, 1, 1);
        cfg.stream   = 0;
        cudaLaunchAttribute attr[1];
        attr[0].id = cudaLaunchAttributeProgrammaticStreamSerialization;
        attr[0].val.programmaticStreamSerializationAllowed = 1;
        cfg.attrs = attr;
        cfg.numAttrs = 1;
        cudaLaunchKernelEx(&cfg, mlp_kernel,
                           vals, distances, W1, b1, W2, b2, out, N);
    }
}